// round 13
// baseline (speedup 1.0000x reference)
#include <cuda_runtime.h>
#include <cuda_bf16.h>
#include <cstdint>

// ===================== problem constants =====================
#define BBATCH 16
#define TSEQ   256
#define CEMB   4096
#define NHEAD  16
#define DHEAD  256

// ===================== scratch (device globals) =====================
static constexpr unsigned long long SZ = 4096ULL * 4096ULL;  // 16.7M
__device__ __nv_bfloat16  g_xh[SZ],  g_xl[SZ];
__device__ __nv_bfloat16  g_wah[3*SZ], g_wal[3*SZ];
__device__ __nv_bfloat16  g_wph[SZ], g_wpl[SZ];
__device__ __nv_bfloat16  g_qh[SZ],  g_ql[SZ],  g_kh[SZ],  g_kl[SZ];
__device__ __nv_bfloat16  g_vth[SZ], g_vtl[SZ];
__device__ __nv_bfloat16  g_ath[SZ], g_atl[SZ];
__device__ __nv_bfloat16  g_y1h[SZ], g_y1l[SZ];
__device__ __nv_bfloat16  g_yh[SZ],  g_yl[SZ];

// ===================== helpers =====================
#define SMEM_SWIZZLE_128B(o) ((o) ^ (((o) >> 3) & 0x70))

__device__ __forceinline__ uint32_t smem_to_u32(const void* p) {
    uint32_t a;
    asm("{ .reg .u64 t; cvta.to.shared.u64 t, %1; cvt.u32.u64 %0, t; }" : "=r"(a) : "l"(p));
    return a;
}
__device__ __forceinline__ void ldsm_x4(uint32_t& r0, uint32_t& r1, uint32_t& r2, uint32_t& r3,
                                        uint32_t a) {
    asm volatile("ldmatrix.sync.aligned.m8n8.x4.shared.b16 {%0,%1,%2,%3}, [%4];"
                 : "=r"(r0), "=r"(r1), "=r"(r2), "=r"(r3) : "r"(a));
}
__device__ __forceinline__ void cp16(uint32_t dst, const void* src) {
    asm volatile("cp.async.cg.shared.global [%0], [%1], 16;" :: "r"(dst), "l"(src));
}
#define CP_COMMIT() asm volatile("cp.async.commit_group;" ::: "memory")
#define CP_WAIT1()  asm volatile("cp.async.wait_group 1;" ::: "memory")

__device__ __forceinline__ void mma16816(float* c, const uint32_t* a, const uint32_t* b) {
    asm volatile(
        "mma.sync.aligned.m16n8k16.row.col.f32.bf16.bf16.f32 "
        "{%0,%1,%2,%3}, {%4,%5,%6,%7}, {%8,%9}, {%0,%1,%2,%3};"
        : "+f"(c[0]), "+f"(c[1]), "+f"(c[2]), "+f"(c[3])
        : "r"(a[0]), "r"(a[1]), "r"(a[2]), "r"(a[3]), "r"(b[0]), "r"(b[1]));
}

__device__ __forceinline__ void split1(float v, __nv_bfloat16& h, __nv_bfloat16& l) {
    h = __float2bfloat16_rn(v);
    l = __float2bfloat16_rn(v - __bfloat162float(h));
}

// ===================== HMMA GEMM =====================
// D = A @ B^T, A:[M,K] row-major, B:[N,K] row-major, both split hi/lo bf16.
// D = Ah*Bh + Al*Bh + Ah*Bl (fp32 accum in registers).
// CTA tile 64x128, warp tile 32x32 (2x4 warps), BK=64 (128B rows, SW128),
// 2-stage cp.async pipeline (48KB/stage, 96KB/CTA) -> 2 CTAs per SM.
// MODE 0: fp32 out + bias. MODE 1: split hi/lo bf16 out.
// MODE 2: scale+causal+relu, split. MODE 3: fused qkv epilogue (q/k gather-split,
//         v transpose-split via smem staging).
// ktrim: clamp K-chunks to (rowBase/64)+1 (A has causal zero columns beyond).

static constexpr int STAGE_BYTES = 49152;            // Ah 8K | Al 8K | Bh 16K | Bl 16K
static constexpr int HG_SMEM = 2 * STAGE_BYTES;      // 98304

template<int MODE>
__global__ __launch_bounds__(256, 2)
void hgemm(const __nv_bfloat16* __restrict__ Ah, const __nv_bfloat16* __restrict__ Al,
           const __nv_bfloat16* __restrict__ Bh, const __nv_bfloat16* __restrict__ Bl,
           float* __restrict__ Cf, __nv_bfloat16* __restrict__ Ch, __nv_bfloat16* __restrict__ Cl,
           __nv_bfloat16* __restrict__ Kh, __nv_bfloat16* __restrict__ Kl,
           __nv_bfloat16* __restrict__ Vh, __nv_bfloat16* __restrict__ Vl,
           const float* __restrict__ bias,
           int K, int lda, int ldb, int ldc,
           long sAb, long sAh_, long sBb, long sBh_, long sCb, long sCh_,
           int nH, float scale, int ktrim)
{
    int tid = threadIdx.x, lane = tid & 31, wid = tid >> 5;
    int warpM = wid >> 2, warpN = wid & 3;            // 2 x 4 warps, warp tile 32x32
    int rowBase = blockIdx.x * 64;
    int colBase = blockIdx.y * 128;

    int z = blockIdx.z, bz = z / nH, hz = z % nH;
    size_t cb = (size_t)bz * sCb + (size_t)hz * sCh_;

    // ---- fully masked tile (MODE 2): zero-fill and exit ----
    if constexpr (MODE == 2) {
        if (colBase >= rowBase + 64) {
            for (int u = tid; u < 64 * 128 / 2; u += 256) {
                int r = u / 64, c2 = (u % 64) * 2;
                size_t o = cb + (size_t)(rowBase + r) * ldc + colBase + c2;
                *(uint32_t*)(Ch + o) = 0u;
                *(uint32_t*)(Cl + o) = 0u;
            }
            return;
        }
    }

    const __nv_bfloat16* pAh = Ah + (size_t)bz * sAb + (size_t)hz * sAh_;
    const __nv_bfloat16* pAl = Al + (size_t)bz * sAb + (size_t)hz * sAh_;
    const __nv_bfloat16* pBh = Bh + (size_t)bz * sBb + (size_t)hz * sBh_;
    const __nv_bfloat16* pBl = Bl + (size_t)bz * sBb + (size_t)hz * sBh_;

    extern __shared__ char smem[];
    uint32_t sb = smem_to_u32(smem);

    // ---- stage loader: Ah/Al 64 rows, Bh/Bl 128 rows, 128B rows, SW128 ----
    auto load_stage = [&](int s, int k0) {
        uint32_t d0 = sb + s * STAGE_BYTES;
        #pragma unroll
        for (int it = 0; it < 2; it++) {          // Ah
            int u = it * 256 + tid;
            int r = u >> 3, c = u & 7;
            cp16(d0 + SMEM_SWIZZLE_128B(r * 128 + c * 16),
                 pAh + (size_t)(rowBase + r) * lda + k0 + c * 8);
        }
        #pragma unroll
        for (int it = 0; it < 2; it++) {          // Al
            int u = it * 256 + tid;
            int r = u >> 3, c = u & 7;
            cp16(d0 + 8192 + SMEM_SWIZZLE_128B(r * 128 + c * 16),
                 pAl + (size_t)(rowBase + r) * lda + k0 + c * 8);
        }
        #pragma unroll
        for (int it = 0; it < 4; it++) {          // Bh
            int u = it * 256 + tid;
            int r = u >> 3, c = u & 7;
            cp16(d0 + 16384 + SMEM_SWIZZLE_128B(r * 128 + c * 16),
                 pBh + (size_t)(colBase + r) * ldb + k0 + c * 8);
        }
        #pragma unroll
        for (int it = 0; it < 4; it++) {          // Bl
            int u = it * 256 + tid;
            int r = u >> 3, c = u & 7;
            cp16(d0 + 32768 + SMEM_SWIZZLE_128B(r * 128 + c * 16),
                 pBl + (size_t)(colBase + r) * ldb + k0 + c * 8);
        }
        CP_COMMIT();
    };

    int nCh = K >> 6;
    if (ktrim) { int lim = (rowBase >> 6) + 1; if (lim < nCh) nCh = lim; }

    load_stage(0, 0);
    load_stage(1, 64);

    float acc[2][4][4] = {};

    int rA_sub = (lane & 7) + ((lane >> 3) & 1) * 8;  int chA = (lane >> 4) & 1;
    int rB_sub = (lane & 7) + ((lane >> 4) & 1) * 8;  int chB = (lane >> 3) & 1;

    for (int i = 0; i < nCh; i++) {
        CP_WAIT1();
        __syncthreads();
        uint32_t st = sb + (i & 1) * STAGE_BYTES;

        #pragma unroll
        for (int kk = 0; kk < 4; kk++) {
            uint32_t ah[2][4], al[2][4], bb[4][2];
            #pragma unroll
            for (int mi = 0; mi < 2; mi++) {
                int rowA = warpM * 32 + mi * 16 + rA_sub;
                uint32_t off = rowA * 128 + (((kk * 2 + chA) ^ (rowA & 7)) << 4);
                ldsm_x4(ah[mi][0], ah[mi][1], ah[mi][2], ah[mi][3], st + off);
            }
            #pragma unroll
            for (int p = 0; p < 2; p++) {
                int rowB = warpN * 32 + p * 16 + rB_sub;
                uint32_t off = rowB * 128 + (((kk * 2 + chB) ^ (rowB & 7)) << 4);
                ldsm_x4(bb[2*p][0], bb[2*p][1], bb[2*p+1][0], bb[2*p+1][1], st + 16384 + off);
            }
            #pragma unroll
            for (int mi = 0; mi < 2; mi++)
                #pragma unroll
                for (int ni = 0; ni < 4; ni++)
                    mma16816(acc[mi][ni], ah[mi], bb[ni]);
            #pragma unroll
            for (int mi = 0; mi < 2; mi++) {
                int rowA = warpM * 32 + mi * 16 + rA_sub;
                uint32_t off = rowA * 128 + (((kk * 2 + chA) ^ (rowA & 7)) << 4);
                ldsm_x4(al[mi][0], al[mi][1], al[mi][2], al[mi][3], st + 8192 + off);
            }
            #pragma unroll
            for (int mi = 0; mi < 2; mi++)
                #pragma unroll
                for (int ni = 0; ni < 4; ni++)
                    mma16816(acc[mi][ni], al[mi], bb[ni]);
            #pragma unroll
            for (int p = 0; p < 2; p++) {
                int rowB = warpN * 32 + p * 16 + rB_sub;
                uint32_t off = rowB * 128 + (((kk * 2 + chB) ^ (rowB & 7)) << 4);
                ldsm_x4(bb[2*p][0], bb[2*p][1], bb[2*p+1][0], bb[2*p+1][1], st + 32768 + off);
            }
            #pragma unroll
            for (int mi = 0; mi < 2; mi++)
                #pragma unroll
                for (int ni = 0; ni < 4; ni++)
                    mma16816(acc[mi][ni], ah[mi], bb[ni]);
        }

        __syncthreads();
        if (i + 2 < nCh) load_stage(i & 1, (i + 2) * 64);
        else CP_COMMIT();
    }

    // ===================== epilogue =====================
    int g = lane >> 2, cq = (lane & 3) * 2;

    if constexpr (MODE == 3) {
        // GEMM1 fused qkv epilogue.
        int region = colBase >> 12;              // 0=q 1=k 2=v
        int hcol   = (colBase & 4095) >> 8;      // head index
        int d0     = colBase & 255;              // 0 or 128
        int bidx   = rowBase >> 8;               // batch
        int tBase  = rowBase & 255;
        size_t zoff = (size_t)(bidx * NHEAD + hcol) * ((size_t)TSEQ * DHEAD);

        if (region < 2) {
            __nv_bfloat16* H = (region == 0) ? Ch : Kh;
            __nv_bfloat16* L = (region == 0) ? Cl : Kl;
            #pragma unroll
            for (int mi = 0; mi < 2; mi++)
                #pragma unroll
                for (int ni = 0; ni < 4; ni++) {
                    int cl = warpN * 32 + ni * 8 + cq;
                    #pragma unroll
                    for (int h = 0; h < 2; h++) {
                        int t = tBase + warpM * 32 + mi * 16 + g + h * 8;
                        float a = acc[mi][ni][2 * h + 0] + bias[colBase + cl];
                        float b = acc[mi][ni][2 * h + 1] + bias[colBase + cl + 1];
                        __nv_bfloat16 ha, la, hb, lb;
                        split1(a, ha, la); split1(b, hb, lb);
                        size_t o = zoff + (size_t)t * DHEAD + d0 + cl;
                        *(__nv_bfloat162*)(H + o) = __halves2bfloat162(ha, hb);
                        *(__nv_bfloat162*)(L + o) = __halves2bfloat162(la, lb);
                    }
                }
        } else {
            // v: stage fp32 tile [64 t][128 d] in smem, then transposed split write.
            float* sf = (float*)smem;            // 64 x 132 floats = 33792 B
            #pragma unroll
            for (int mi = 0; mi < 2; mi++)
                #pragma unroll
                for (int ni = 0; ni < 4; ni++) {
                    int cl = warpN * 32 + ni * 8 + cq;
                    #pragma unroll
                    for (int h = 0; h < 2; h++) {
                        int rl = warpM * 32 + mi * 16 + g + h * 8;
                        sf[rl * 132 + cl]     = acc[mi][ni][2 * h + 0] + bias[colBase + cl];
                        sf[rl * 132 + cl + 1] = acc[mi][ni][2 * h + 1] + bias[colBase + cl + 1];
                    }
                }
            __syncthreads();
            int d = tid >> 1, th0 = (tid & 1) * 32;
            size_t obase = zoff + (size_t)(d0 + d) * TSEQ + tBase + th0;
            #pragma unroll
            for (int p = 0; p < 16; p++) {
                float v0 = sf[(th0 + 2 * p)     * 132 + d];
                float v1 = sf[(th0 + 2 * p + 1) * 132 + d];
                __nv_bfloat16 h0, l0, h1, l1;
                split1(v0, h0, l0); split1(v1, h1, l1);
                *(__nv_bfloat162*)(Vh + obase + 2 * p) = __halves2bfloat162(h0, h1);
                *(__nv_bfloat162*)(Vl + obase + 2 * p) = __halves2bfloat162(l0, l1);
            }
        }
        return;
    }

    #pragma unroll
    for (int mi = 0; mi < 2; mi++) {
        #pragma unroll
        for (int ni = 0; ni < 4; ni++) {
            int r0 = rowBase + warpM * 32 + mi * 16 + g;
            int c0 = colBase + warpN * 32 + ni * 8 + cq;
            #pragma unroll
            for (int h = 0; h < 2; h++) {
                int r = r0 + h * 8;
                float a = acc[mi][ni][2 * h + 0];
                float b = acc[mi][ni][2 * h + 1];
                if constexpr (MODE == 0) {
                    float2 v;
                    v.x = a + bias[c0];  v.y = b + bias[c0 + 1];
                    *(float2*)(Cf + cb + (size_t)r * ldc + c0) = v;
                } else {
                    if constexpr (MODE == 2) {
                        a = (c0     <= r) ? fmaxf(a * scale, 0.f) : 0.f;
                        b = (c0 + 1 <= r) ? fmaxf(b * scale, 0.f) : 0.f;
                    }
                    __nv_bfloat16 ha, la, hb, lb;
                    split1(a, ha, la); split1(b, hb, lb);
                    size_t o = cb + (size_t)r * ldc + c0;
                    *(__nv_bfloat162*)(Ch + o) = __halves2bfloat162(ha, hb);
                    *(__nv_bfloat162*)(Cl + o) = __halves2bfloat162(la, lb);
                }
            }
        }
    }
}

// ===================== prep kernels =====================
__global__ void split_k(const float* __restrict__ s, __nv_bfloat16* __restrict__ h,
                        __nv_bfloat16* __restrict__ l, int n4) {
    int i = blockIdx.x * blockDim.x + threadIdx.x;
    if (i >= n4) return;
    float4 v = *(const float4*)(s + (size_t)i * 4);
    __nv_bfloat16 h0, h1, h2, h3, l0, l1, l2, l3;
    split1(v.x, h0, l0); split1(v.y, h1, l1); split1(v.z, h2, l2); split1(v.w, h3, l3);
    *(__nv_bfloat162*)(h + (size_t)i * 4)     = __halves2bfloat162(h0, h1);
    *(__nv_bfloat162*)(h + (size_t)i * 4 + 2) = __halves2bfloat162(h2, h3);
    *(__nv_bfloat162*)(l + (size_t)i * 4)     = __halves2bfloat162(l0, l1);
    *(__nv_bfloat162*)(l + (size_t)i * 4 + 2) = __halves2bfloat162(l2, l3);
}

// transpose + split: dst[s_col, s_row] = src[s_row, s_col]  (weights)
__global__ void tsplit_k(const float* __restrict__ src, __nv_bfloat16* __restrict__ h,
                         __nv_bfloat16* __restrict__ l, int ld_src, int ld_dst) {
    __shared__ float t[32][33];
    const float* s = src;
    int c0 = blockIdx.x * 32, r0 = blockIdx.y * 32;
    int tx = threadIdx.x, ty = threadIdx.y;
    #pragma unroll
    for (int j = 0; j < 4; j++)
        t[ty + 8 * j][tx] = s[(size_t)(r0 + ty + 8 * j) * ld_src + c0 + tx];
    __syncthreads();
    #pragma unroll
    for (int j = 0; j < 4; j++) {
        float v = t[tx][ty + 8 * j];
        __nv_bfloat16 hh, ll;
        split1(v, hh, ll);
        size_t o = (size_t)(c0 + ty + 8 * j) * ld_dst + r0 + tx;
        h[o] = hh; l[o] = ll;
    }
}

// ===================== host =====================
extern "C" void kernel_launch(void* const* d_in, const int* in_sizes, int n_in,
                              void* d_out, int out_size)
{
    const float* x      = (const float*)d_in[0];
    const float* W_attn = (const float*)d_in[1];
    const float* b_attn = (const float*)d_in[2];
    const float* W_proj = (const float*)d_in[3];
    const float* b_proj = (const float*)d_in[4];
    float* out = (float*)d_out;

    __nv_bfloat16 *xh, *xl, *wah, *wal, *wph, *wpl;
    __nv_bfloat16 *qh, *ql, *kh, *kl, *vth, *vtl, *ath, *atl, *y1h, *y1l, *yh, *yl;
    cudaGetSymbolAddress((void**)&xh, g_xh);   cudaGetSymbolAddress((void**)&xl, g_xl);
    cudaGetSymbolAddress((void**)&wah, g_wah); cudaGetSymbolAddress((void**)&wal, g_wal);
    cudaGetSymbolAddress((void**)&wph, g_wph); cudaGetSymbolAddress((void**)&wpl, g_wpl);
    cudaGetSymbolAddress((void**)&qh, g_qh);   cudaGetSymbolAddress((void**)&ql, g_ql);
    cudaGetSymbolAddress((void**)&kh, g_kh);   cudaGetSymbolAddress((void**)&kl, g_kl);
    cudaGetSymbolAddress((void**)&vth, g_vth); cudaGetSymbolAddress((void**)&vtl, g_vtl);
    cudaGetSymbolAddress((void**)&ath, g_ath); cudaGetSymbolAddress((void**)&atl, g_atl);
    cudaGetSymbolAddress((void**)&y1h, g_y1h); cudaGetSymbolAddress((void**)&y1l, g_y1l);
    cudaGetSymbolAddress((void**)&yh, g_yh);   cudaGetSymbolAddress((void**)&yl, g_yl);

    cudaFuncSetAttribute(hgemm<0>, cudaFuncAttributeMaxDynamicSharedMemorySize, HG_SMEM);
    cudaFuncSetAttribute(hgemm<1>, cudaFuncAttributeMaxDynamicSharedMemorySize, HG_SMEM);
    cudaFuncSetAttribute(hgemm<2>, cudaFuncAttributeMaxDynamicSharedMemorySize, HG_SMEM);
    cudaFuncSetAttribute(hgemm<3>, cudaFuncAttributeMaxDynamicSharedMemorySize, HG_SMEM);

    const int C3 = 3 * CEMB;                 // 12288
    const long TD = (long)TSEQ * DHEAD;      // 65536
    const float scale = 0.0625f;

    // prep: split x, transpose+split weights
    split_k<<<16384, 256>>>(x, xh, xl, (int)(SZ / 4));
    tsplit_k<<<dim3(C3 / 32, CEMB / 32, 1), dim3(32, 8)>>>(W_attn, wah, wal, C3, CEMB);
    tsplit_k<<<dim3(CEMB / 32, CEMB / 32, 1), dim3(32, 8)>>>(W_proj, wph, wpl, CEMB, CEMB);

    // GEMM1 (fused): q/k gather-split + v transpose-split, bias added
    hgemm<3><<<dim3(64, 96, 1), 256, HG_SMEM>>>(
        xh, xl, wah, wal, nullptr, qh, ql, kh, kl, vth, vtl, b_attn,
        CEMB, CEMB, CEMB, 0, 0, 0, 0, 0, 0, 0, 1, 0.f, 0);

    // K2: att = split(relu(causal(q @ k^T * scale)))
    hgemm<2><<<dim3(4, 2, 256), 256, HG_SMEM>>>(
        qh, ql, kh, kl, nullptr, ath, atl, nullptr, nullptr, nullptr, nullptr, nullptr,
        DHEAD, DHEAD, DHEAD, TSEQ,
        (long)NHEAD * TD, TD, (long)NHEAD * TD, TD, (long)NHEAD * TD, TD,
        NHEAD, scale, 0);

    // K3: y1 = att @ v   (causal K-trim: att cols > rowBase+63 are zero)
    hgemm<1><<<dim3(4, 2, 256), 256, HG_SMEM>>>(
        ath, atl, vth, vtl, nullptr, y1h, y1l, nullptr, nullptr, nullptr, nullptr, nullptr,
        TSEQ, TSEQ, TSEQ, DHEAD,
        (long)NHEAD * TD, TD, (long)NHEAD * TD, TD, (long)NHEAD * TD, TD,
        NHEAD, 0.f, 1);

    // K4: y = y1 @ v   (written into [B,T,C] head slices)
    hgemm<1><<<dim3(4, 2, 256), 256, HG_SMEM>>>(
        y1h, y1l, vth, vtl, nullptr, yh, yl, nullptr, nullptr, nullptr, nullptr, nullptr,
        TSEQ, DHEAD, TSEQ, CEMB,
        (long)NHEAD * TD, TD, (long)NHEAD * TD, TD, (long)TSEQ * CEMB, (long)DHEAD,
        NHEAD, 0.f, 0);

    // GEMM5: out = y @ W_proj + b_proj
    hgemm<0><<<dim3(64, 32, 1), 256, HG_SMEM>>>(
        yh, yl, wph, wpl, out, nullptr, nullptr, nullptr, nullptr, nullptr, nullptr, b_proj,
        CEMB, CEMB, CEMB, CEMB, 0, 0, 0, 0, 0, 0, 1, 0.f, 0);
}

// round 17
// speedup vs baseline: 1.0275x; 1.0275x over previous
#include <cuda_runtime.h>
#include <cuda_bf16.h>
#include <cstdint>

// ===================== problem constants =====================
#define BBATCH 16
#define TSEQ   256
#define CEMB   4096
#define NHEAD  16
#define DHEAD  256

// ===================== scratch (device globals) =====================
static constexpr unsigned long long SZ = 4096ULL * 4096ULL;  // 16.7M
__device__ float          g_qkv[16ULL * 256 * 12288];
__device__ __nv_bfloat16  g_xh[SZ],  g_xl[SZ];
__device__ __nv_bfloat16  g_wah[3*SZ], g_wal[3*SZ];
__device__ __nv_bfloat16  g_wph[SZ], g_wpl[SZ];
__device__ __nv_bfloat16  g_qh[SZ],  g_ql[SZ],  g_kh[SZ],  g_kl[SZ];
__device__ __nv_bfloat16  g_vth[SZ], g_vtl[SZ];
__device__ __nv_bfloat16  g_ath[SZ], g_atl[SZ];
__device__ __nv_bfloat16  g_y1h[SZ], g_y1l[SZ];
__device__ __nv_bfloat16  g_yh[SZ],  g_yl[SZ];

// ===================== helpers =====================
#define SMEM_SWIZZLE_128B(o) ((o) ^ (((o) >> 3) & 0x70))

__device__ __forceinline__ uint32_t smem_to_u32(const void* p) {
    uint32_t a;
    asm("{ .reg .u64 t; cvta.to.shared.u64 t, %1; cvt.u32.u64 %0, t; }" : "=r"(a) : "l"(p));
    return a;
}
__device__ __forceinline__ void ldsm_x4(uint32_t& r0, uint32_t& r1, uint32_t& r2, uint32_t& r3,
                                        uint32_t a) {
    asm volatile("ldmatrix.sync.aligned.m8n8.x4.shared.b16 {%0,%1,%2,%3}, [%4];"
                 : "=r"(r0), "=r"(r1), "=r"(r2), "=r"(r3) : "r"(a));
}
__device__ __forceinline__ void cp16(uint32_t dst, const void* src) {
    asm volatile("cp.async.cg.shared.global [%0], [%1], 16;" :: "r"(dst), "l"(src));
}
#define CP_COMMIT() asm volatile("cp.async.commit_group;" ::: "memory")
#define CP_WAIT1()  asm volatile("cp.async.wait_group 1;" ::: "memory")

__device__ __forceinline__ void mma16816(float* c, const uint32_t* a, const uint32_t* b) {
    asm volatile(
        "mma.sync.aligned.m16n8k16.row.col.f32.bf16.bf16.f32 "
        "{%0,%1,%2,%3}, {%4,%5,%6,%7}, {%8,%9}, {%0,%1,%2,%3};"
        : "+f"(c[0]), "+f"(c[1]), "+f"(c[2]), "+f"(c[3])
        : "r"(a[0]), "r"(a[1]), "r"(a[2]), "r"(a[3]), "r"(b[0]), "r"(b[1]));
}

__device__ __forceinline__ void split1(float v, __nv_bfloat16& h, __nv_bfloat16& l) {
    h = __float2bfloat16_rn(v);
    l = __float2bfloat16_rn(v - __bfloat162float(h));
}

// ===================== HMMA GEMM =====================
// D = A @ B^T, A:[M,K] row-major, B:[N,K] row-major, both split hi/lo bf16.
// D = Ah*Bh + Al*Bh + Ah*Bl (fp32 accum in registers).
// CTA tile 64x128, warp tile 32x32 (2x4 warps), BK=64 (128B rows, SW128),
// 2-stage cp.async pipeline (48KB/stage, 96KB/CTA) -> 2 CTAs per SM.
// MODE 0: fp32 out + bias. MODE 1: split hi/lo bf16 out. MODE 2: scale+causal+relu, split.
// ktrim: clamp K-chunks to (rowBase/64)+1 (A has causal zero columns beyond).

static constexpr int STAGE_BYTES = 49152;            // Ah 8K | Al 8K | Bh 16K | Bl 16K
static constexpr int HG_SMEM = 2 * STAGE_BYTES;      // 98304

template<int MODE>
__global__ __launch_bounds__(256, 2)
void hgemm(const __nv_bfloat16* __restrict__ Ah, const __nv_bfloat16* __restrict__ Al,
           const __nv_bfloat16* __restrict__ Bh, const __nv_bfloat16* __restrict__ Bl,
           float* __restrict__ Cf, __nv_bfloat16* __restrict__ Ch, __nv_bfloat16* __restrict__ Cl,
           const float* __restrict__ bias,
           int K, int lda, int ldb, int ldc,
           long sAb, long sAh_, long sBb, long sBh_, long sCb, long sCh_,
           int nH, float scale, int ktrim)
{
    int tid = threadIdx.x, lane = tid & 31, wid = tid >> 5;
    int warpM = wid >> 2, warpN = wid & 3;            // 2 x 4 warps, warp tile 32x32
    int rowBase = blockIdx.x * 64;
    int colBase = blockIdx.y * 128;

    int z = blockIdx.z, bz = z / nH, hz = z % nH;
    size_t cb = (size_t)bz * sCb + (size_t)hz * sCh_;

    // ---- fully masked tile (MODE 2): zero-fill and exit ----
    if constexpr (MODE == 2) {
        if (colBase >= rowBase + 64) {
            for (int u = tid; u < 64 * 128 / 2; u += 256) {
                int r = u / 64, c2 = (u % 64) * 2;
                size_t o = cb + (size_t)(rowBase + r) * ldc + colBase + c2;
                *(uint32_t*)(Ch + o) = 0u;
                *(uint32_t*)(Cl + o) = 0u;
            }
            return;
        }
    }

    const __nv_bfloat16* pAh = Ah + (size_t)bz * sAb + (size_t)hz * sAh_;
    const __nv_bfloat16* pAl = Al + (size_t)bz * sAb + (size_t)hz * sAh_;
    const __nv_bfloat16* pBh = Bh + (size_t)bz * sBb + (size_t)hz * sBh_;
    const __nv_bfloat16* pBl = Bl + (size_t)bz * sBb + (size_t)hz * sBh_;

    extern __shared__ char smem[];
    uint32_t sb = smem_to_u32(smem);

    // ---- stage loader: Ah/Al 64 rows, Bh/Bl 128 rows, 128B rows, SW128 ----
    auto load_stage = [&](int s, int k0) {
        uint32_t d0 = sb + s * STAGE_BYTES;
        #pragma unroll
        for (int it = 0; it < 2; it++) {          // Ah
            int u = it * 256 + tid;
            int r = u >> 3, c = u & 7;
            cp16(d0 + SMEM_SWIZZLE_128B(r * 128 + c * 16),
                 pAh + (size_t)(rowBase + r) * lda + k0 + c * 8);
        }
        #pragma unroll
        for (int it = 0; it < 2; it++) {          // Al
            int u = it * 256 + tid;
            int r = u >> 3, c = u & 7;
            cp16(d0 + 8192 + SMEM_SWIZZLE_128B(r * 128 + c * 16),
                 pAl + (size_t)(rowBase + r) * lda + k0 + c * 8);
        }
        #pragma unroll
        for (int it = 0; it < 4; it++) {          // Bh
            int u = it * 256 + tid;
            int r = u >> 3, c = u & 7;
            cp16(d0 + 16384 + SMEM_SWIZZLE_128B(r * 128 + c * 16),
                 pBh + (size_t)(colBase + r) * ldb + k0 + c * 8);
        }
        #pragma unroll
        for (int it = 0; it < 4; it++) {          // Bl
            int u = it * 256 + tid;
            int r = u >> 3, c = u & 7;
            cp16(d0 + 32768 + SMEM_SWIZZLE_128B(r * 128 + c * 16),
                 pBl + (size_t)(colBase + r) * ldb + k0 + c * 8);
        }
        CP_COMMIT();
    };

    int nCh = K >> 6;
    if (ktrim) { int lim = (rowBase >> 6) + 1; if (lim < nCh) nCh = lim; }

    load_stage(0, 0);
    load_stage(1, nCh > 1 ? 64 : 0);

    float acc[2][4][4] = {};

    int rA_sub = (lane & 7) + ((lane >> 3) & 1) * 8;  int chA = (lane >> 4) & 1;
    int rB_sub = (lane & 7) + ((lane >> 4) & 1) * 8;  int chB = (lane >> 3) & 1;

    for (int i = 0; i < nCh; i++) {
        CP_WAIT1();
        __syncthreads();
        uint32_t st = sb + (i & 1) * STAGE_BYTES;

        #pragma unroll
        for (int kk = 0; kk < 4; kk++) {
            uint32_t ah[2][4], al[2][4], bb[4][2];
            #pragma unroll
            for (int mi = 0; mi < 2; mi++) {
                int rowA = warpM * 32 + mi * 16 + rA_sub;
                uint32_t off = rowA * 128 + (((kk * 2 + chA) ^ (rowA & 7)) << 4);
                ldsm_x4(ah[mi][0], ah[mi][1], ah[mi][2], ah[mi][3], st + off);
            }
            #pragma unroll
            for (int p = 0; p < 2; p++) {
                int rowB = warpN * 32 + p * 16 + rB_sub;
                uint32_t off = rowB * 128 + (((kk * 2 + chB) ^ (rowB & 7)) << 4);
                ldsm_x4(bb[2*p][0], bb[2*p][1], bb[2*p+1][0], bb[2*p+1][1], st + 16384 + off);
            }
            #pragma unroll
            for (int mi = 0; mi < 2; mi++)
                #pragma unroll
                for (int ni = 0; ni < 4; ni++)
                    mma16816(acc[mi][ni], ah[mi], bb[ni]);
            #pragma unroll
            for (int mi = 0; mi < 2; mi++) {
                int rowA = warpM * 32 + mi * 16 + rA_sub;
                uint32_t off = rowA * 128 + (((kk * 2 + chA) ^ (rowA & 7)) << 4);
                ldsm_x4(al[mi][0], al[mi][1], al[mi][2], al[mi][3], st + 8192 + off);
            }
            #pragma unroll
            for (int mi = 0; mi < 2; mi++)
                #pragma unroll
                for (int ni = 0; ni < 4; ni++)
                    mma16816(acc[mi][ni], al[mi], bb[ni]);
            #pragma unroll
            for (int p = 0; p < 2; p++) {
                int rowB = warpN * 32 + p * 16 + rB_sub;
                uint32_t off = rowB * 128 + (((kk * 2 + chB) ^ (rowB & 7)) << 4);
                ldsm_x4(bb[2*p][0], bb[2*p][1], bb[2*p+1][0], bb[2*p+1][1], st + 32768 + off);
            }
            #pragma unroll
            for (int mi = 0; mi < 2; mi++)
                #pragma unroll
                for (int ni = 0; ni < 4; ni++)
                    mma16816(acc[mi][ni], ah[mi], bb[ni]);
        }

        __syncthreads();
        if (i + 2 < nCh) load_stage(i & 1, (i + 2) * 64);
        else CP_COMMIT();
    }

    // ===================== epilogue =====================
    int g = lane >> 2, cq = (lane & 3) * 2;

    #pragma unroll
    for (int mi = 0; mi < 2; mi++) {
        #pragma unroll
        for (int ni = 0; ni < 4; ni++) {
            int r0 = rowBase + warpM * 32 + mi * 16 + g;
            int c0 = colBase + warpN * 32 + ni * 8 + cq;
            #pragma unroll
            for (int h = 0; h < 2; h++) {
                int r = r0 + h * 8;
                float a = acc[mi][ni][2 * h + 0];
                float b = acc[mi][ni][2 * h + 1];
                if constexpr (MODE == 0) {
                    float2 v;
                    v.x = a + bias[c0];  v.y = b + bias[c0 + 1];
                    *(float2*)(Cf + cb + (size_t)r * ldc + c0) = v;
                } else {
                    if constexpr (MODE == 2) {
                        a = (c0     <= r) ? fmaxf(a * scale, 0.f) : 0.f;
                        b = (c0 + 1 <= r) ? fmaxf(b * scale, 0.f) : 0.f;
                    }
                    __nv_bfloat16 ha, la, hb, lb;
                    split1(a, ha, la); split1(b, hb, lb);
                    size_t o = cb + (size_t)r * ldc + c0;
                    *(__nv_bfloat162*)(Ch + o) = __halves2bfloat162(ha, hb);
                    *(__nv_bfloat162*)(Cl + o) = __halves2bfloat162(la, lb);
                }
            }
        }
    }
}

// ===================== prep kernels =====================
__global__ void split_k(const float* __restrict__ s, __nv_bfloat16* __restrict__ h,
                        __nv_bfloat16* __restrict__ l, int n4) {
    int i = blockIdx.x * blockDim.x + threadIdx.x;
    if (i >= n4) return;
    float4 v = *(const float4*)(s + (size_t)i * 4);
    __nv_bfloat16 h0, h1, h2, h3, l0, l1, l2, l3;
    split1(v.x, h0, l0); split1(v.y, h1, l1); split1(v.z, h2, l2); split1(v.w, h3, l3);
    *(__nv_bfloat162*)(h + (size_t)i * 4)     = __halves2bfloat162(h0, h1);
    *(__nv_bfloat162*)(h + (size_t)i * 4 + 2) = __halves2bfloat162(h2, h3);
    *(__nv_bfloat162*)(l + (size_t)i * 4)     = __halves2bfloat162(l0, l1);
    *(__nv_bfloat162*)(l + (size_t)i * 4 + 2) = __halves2bfloat162(l2, l3);
}

// transpose + split: dst[s_col, s_row] = src[s_row, s_col]
__global__ void tsplit_k(const float* __restrict__ src, __nv_bfloat16* __restrict__ h,
                         __nv_bfloat16* __restrict__ l,
                         int ld_src, int ld_dst, long src_zb, long src_zh, long dst_z, int nH) {
    __shared__ float t[32][33];
    int z = blockIdx.z, bz = z / nH, hz = z % nH;
    const float* s = src + (size_t)bz * src_zb + (size_t)hz * src_zh;
    __nv_bfloat16* dh = h + (size_t)z * dst_z;
    __nv_bfloat16* dl = l + (size_t)z * dst_z;
    int c0 = blockIdx.x * 32, r0 = blockIdx.y * 32;
    int tx = threadIdx.x, ty = threadIdx.y;
    #pragma unroll
    for (int j = 0; j < 4; j++)
        t[ty + 8 * j][tx] = s[(size_t)(r0 + ty + 8 * j) * ld_src + c0 + tx];
    __syncthreads();
    #pragma unroll
    for (int j = 0; j < 4; j++) {
        float v = t[tx][ty + 8 * j];
        __nv_bfloat16 hh, ll;
        split1(v, hh, ll);
        size_t o = (size_t)(c0 + ty + 8 * j) * ld_dst + r0 + tx;
        dh[o] = hh; dl[o] = ll;
    }
}

// head-gather + split (q, k): dst[z, t, d] = src[b, t, hz*D + d]
__global__ void gsplit_k(const float* __restrict__ src, __nv_bfloat16* __restrict__ h,
                         __nv_bfloat16* __restrict__ l,
                         int ld_src, long src_zb, long src_zh, long dst_z, int nH) {
    int z = blockIdx.z, bz = z / nH, hz = z % nH;
    const float* s = src + (size_t)bz * src_zb + (size_t)hz * src_zh;
    int idx = blockIdx.x * blockDim.x + threadIdx.x;
    int e = idx * 4;
    int r = e >> 8, c = e & 255;
    float4 v = *(const float4*)(s + (size_t)r * ld_src + c);
    __nv_bfloat16 h0, h1, h2, h3, l0, l1, l2, l3;
    split1(v.x, h0, l0); split1(v.y, h1, l1); split1(v.z, h2, l2); split1(v.w, h3, l3);
    size_t o = (size_t)z * dst_z + (size_t)r * 256 + c;
    *(__nv_bfloat162*)(h + o)     = __halves2bfloat162(h0, h1);
    *(__nv_bfloat162*)(h + o + 2) = __halves2bfloat162(h2, h3);
    *(__nv_bfloat162*)(l + o)     = __halves2bfloat162(l0, l1);
    *(__nv_bfloat162*)(l + o + 2) = __halves2bfloat162(l2, l3);
}

// ===================== host =====================
extern "C" void kernel_launch(void* const* d_in, const int* in_sizes, int n_in,
                              void* d_out, int out_size)
{
    const float* x      = (const float*)d_in[0];
    const float* W_attn = (const float*)d_in[1];
    const float* b_attn = (const float*)d_in[2];
    const float* W_proj = (const float*)d_in[3];
    const float* b_proj = (const float*)d_in[4];
    float* out = (float*)d_out;

    float *qkv;
    __nv_bfloat16 *xh, *xl, *wah, *wal, *wph, *wpl;
    __nv_bfloat16 *qh, *ql, *kh, *kl, *vth, *vtl, *ath, *atl, *y1h, *y1l, *yh, *yl;
    cudaGetSymbolAddress((void**)&qkv, g_qkv);
    cudaGetSymbolAddress((void**)&xh, g_xh);   cudaGetSymbolAddress((void**)&xl, g_xl);
    cudaGetSymbolAddress((void**)&wah, g_wah); cudaGetSymbolAddress((void**)&wal, g_wal);
    cudaGetSymbolAddress((void**)&wph, g_wph); cudaGetSymbolAddress((void**)&wpl, g_wpl);
    cudaGetSymbolAddress((void**)&qh, g_qh);   cudaGetSymbolAddress((void**)&ql, g_ql);
    cudaGetSymbolAddress((void**)&kh, g_kh);   cudaGetSymbolAddress((void**)&kl, g_kl);
    cudaGetSymbolAddress((void**)&vth, g_vth); cudaGetSymbolAddress((void**)&vtl, g_vtl);
    cudaGetSymbolAddress((void**)&ath, g_ath); cudaGetSymbolAddress((void**)&atl, g_atl);
    cudaGetSymbolAddress((void**)&y1h, g_y1h); cudaGetSymbolAddress((void**)&y1l, g_y1l);
    cudaGetSymbolAddress((void**)&yh, g_yh);   cudaGetSymbolAddress((void**)&yl, g_yl);

    cudaFuncSetAttribute(hgemm<0>, cudaFuncAttributeMaxDynamicSharedMemorySize, HG_SMEM);
    cudaFuncSetAttribute(hgemm<1>, cudaFuncAttributeMaxDynamicSharedMemorySize, HG_SMEM);
    cudaFuncSetAttribute(hgemm<2>, cudaFuncAttributeMaxDynamicSharedMemorySize, HG_SMEM);

    const int C3 = 3 * CEMB;                 // 12288
    const long TD = (long)TSEQ * DHEAD;      // 65536
    const float scale = 0.0625f;

    // prep: split x, transpose+split weights
    split_k<<<16384, 256>>>(x, xh, xl, (int)(SZ / 4));
    tsplit_k<<<dim3(C3 / 32, CEMB / 32, 1), dim3(32, 8)>>>(W_attn, wah, wal, C3, CEMB, 0, 0, 0, 1);
    tsplit_k<<<dim3(CEMB / 32, CEMB / 32, 1), dim3(32, 8)>>>(W_proj, wph, wpl, CEMB, CEMB, 0, 0, 0, 1);

    // GEMM1: qkv = x @ W_attn + b_attn   (fp32 out)
    hgemm<0><<<dim3(64, 96, 1), 256, HG_SMEM>>>(
        xh, xl, wah, wal, qkv, nullptr, nullptr, b_attn,
        CEMB, CEMB, CEMB, C3, 0, 0, 0, 0, 0, 0, 1, 0.f, 0);

    // prep heads: q, k gather+split; v transpose+split
    gsplit_k<<<dim3(64, 1, 256), 256>>>(qkv,        qh, ql, C3, (long)TSEQ * C3, DHEAD, TD, NHEAD);
    gsplit_k<<<dim3(64, 1, 256), 256>>>(qkv + CEMB, kh, kl, C3, (long)TSEQ * C3, DHEAD, TD, NHEAD);
    tsplit_k<<<dim3(8, 8, 256), dim3(32, 8)>>>(qkv + 2 * CEMB, vth, vtl,
        C3, TSEQ, (long)TSEQ * C3, DHEAD, TD, NHEAD);

    // K2: att = split(relu(causal(q @ k^T * scale)))
    hgemm<2><<<dim3(4, 2, 256), 256, HG_SMEM>>>(
        qh, ql, kh, kl, nullptr, ath, atl, nullptr,
        DHEAD, DHEAD, DHEAD, TSEQ,
        (long)NHEAD * TD, TD, (long)NHEAD * TD, TD, (long)NHEAD * TD, TD,
        NHEAD, scale, 0);

    // K3: y1 = att @ v   (causal K-trim: att cols > rowBase+63 are zero)
    hgemm<1><<<dim3(4, 2, 256), 256, HG_SMEM>>>(
        ath, atl, vth, vtl, nullptr, y1h, y1l, nullptr,
        TSEQ, TSEQ, TSEQ, DHEAD,
        (long)NHEAD * TD, TD, (long)NHEAD * TD, TD, (long)NHEAD * TD, TD,
        NHEAD, 0.f, 1);

    // K4: y = y1 @ v   (written into [B,T,C] head slices)
    hgemm<1><<<dim3(4, 2, 256), 256, HG_SMEM>>>(
        y1h, y1l, vth, vtl, nullptr, yh, yl, nullptr,
        TSEQ, DHEAD, TSEQ, CEMB,
        (long)NHEAD * TD, TD, (long)NHEAD * TD, TD, (long)TSEQ * CEMB, (long)DHEAD,
        NHEAD, 0.f, 0);

    // GEMM5: out = y @ W_proj + b_proj
    hgemm<0><<<dim3(64, 32, 1), 256, HG_SMEM>>>(
        yh, yl, wph, wpl, out, nullptr, nullptr, b_proj,
        CEMB, CEMB, CEMB, CEMB, 0, 0, 0, 0, 0, 0, 1, 0.f, 0);
}